// round 6
// baseline (speedup 1.0000x reference)
#include <cuda_runtime.h>
#include <cuda_fp16.h>
#include <cstdint>

// ==========================================================================
// LSTM (relu candidate/output) + linear head, mma.sync m16n8k16 fp16.
// B=65536, T=12, F=1, H=128.  CTA = 128 batch rows, 512 threads, grid 512.
// R6: weights persist in registers as the MMA A-operand (loaded once);
//     h-state is the streamed B-operand via ldmatrix.trans on hT[unit][batch].
//     Per-step smem traffic halved; zero weight re-streaming.
// ==========================================================================

#define TT       12
#define HH       128
#define GG       512
#define MTILE    128
#define NTHREADS 512
#define PADH     136                    // halfs per hT/stage row (128 + 8 pad)
#define ROWB     (PADH * 2)             // 272 bytes

// ---- shared memory layout (bytes) ----
#define HT0_OFF   0
#define HT_BYTES  (HH * ROWB)           // 34816 per buffer
#define HT1_OFF   (HT0_OFF + HT_BYTES)
#define XS_OFF    (HT1_OFF + HT_BYTES)  // float[12][128] x transposed
#define WD_OFF    (XS_OFF + TT*MTILE*4) // float[128]
#define RED_OFF   (WD_OFF + 512)        // float[128*4] head partials
#define STAGE_OFF (RED_OFF + MTILE*4*4) // weight staging chunk 128 x ROWB
#define SMEM_TOTAL (STAGE_OFF + 128*ROWB)   // 113152

__device__ __forceinline__ uint32_t s2u(const void* p) {
    uint32_t a;
    asm("{ .reg .u64 t; cvta.to.shared.u64 t, %1; cvt.u32.u64 %0, t; }" : "=r"(a) : "l"(p));
    return a;
}

#define LDSM4(r0, r1, r2, r3, addr) \
    asm volatile("ldmatrix.sync.aligned.m8n8.x4.shared.b16 {%0,%1,%2,%3}, [%4];" \
                 : "=r"(r0), "=r"(r1), "=r"(r2), "=r"(r3) : "r"(addr))

#define LDSM4T(r0, r1, r2, r3, addr) \
    asm volatile("ldmatrix.sync.aligned.m8n8.x4.trans.shared.b16 {%0,%1,%2,%3}, [%4];" \
                 : "=r"(r0), "=r"(r1), "=r"(r2), "=r"(r3) : "r"(addr))

#define MMA16816(d0, d1, d2, d3, a0, a1, a2, a3, b0, b1) \
    asm volatile("mma.sync.aligned.m16n8k16.row.col.f32.f16.f16.f32 " \
                 "{%0,%1,%2,%3}, {%4,%5,%6,%7}, {%8,%9}, {%0,%1,%2,%3};" \
                 : "+f"(d0), "+f"(d1), "+f"(d2), "+f"(d3) \
                 : "r"(a0), "r"(a1), "r"(a2), "r"(a3), "r"(b0), "r"(b1))

// sigmoid(v) = 0.5*tanh(0.5v)+0.5  (single MUFU.TANH)
__device__ __forceinline__ float sigmoid_f(float v) {
    float t;
    asm("tanh.approx.f32 %0, %1;" : "=f"(t) : "f"(0.5f * v));
    return fmaf(0.5f, t, 0.5f);
}

__global__ __launch_bounds__(NTHREADS, 1)
void lstm_kernel(const float* __restrict__ x, const float* __restrict__ kern,
                 const float* __restrict__ rk, const float* __restrict__ bias,
                 const float* __restrict__ Wd, const float* __restrict__ bd,
                 float* __restrict__ out) {
    extern __shared__ char smem[];
    const uint32_t base = s2u(smem);
    const int tid  = threadIdx.x;
    const int lane = tid & 31;
    const int wid  = tid >> 5;          // 0..15: gate-row group (32 perm rows)
    const int t4   = lane >> 2;         // 0..7
    const int j    = lane & 3;          // 0..3: batch column pair within n8 tile
    const int u_thr = 8 * wid + t4;     // this thread's hidden unit
    const int b0   = blockIdx.x * MTILE;

    float* xs  = (float*)(smem + XS_OFF);
    float* wdx = (float*)(smem + WD_OFF);
    float* red = (float*)(smem + RED_OFF);
    __half* stage = (__half*)(smem + STAGE_OFF);

    // ---- stage x (transposed [t][b]) and Wd ----
    for (int i = tid; i < TT * MTILE; i += NTHREADS) {
        int t = i >> 7, b = i & 127;
        xs[i] = x[(size_t)(b0 + b) * TT + t];
    }
    if (tid < HH) wdx[tid] = Wd[tid];

    // ---- weights -> registers (A operand), 4 staging chunks ----
    // perm row n = 32*w + l,  l = 16*(g>>1) + 8*(g&1) + t4,  unit u = 8*w + t4.
    // W_perm[n][k] = rk[k][g*128 + u]   (z = h @ rkernel)
    uint32_t a[2][8][4];
    const uint32_t lrow = (uint32_t)((lane & 7) + (lane & 8));
    const uint32_t lcol = (uint32_t)((lane >> 4) << 4);
    for (int ch = 0; ch < 4; ch++) {
        __syncthreads();
        for (int i = tid; i < 128 * 128; i += NTHREADS) {
            int nl = i >> 7, k = i & 127;
            int n = ch * 128 + nl;
            int wg = n >> 5, l = n & 31;
            int g = 2 * (l >> 4) + ((l >> 3) & 1);
            int uu = 8 * wg + (l & 7);
            stage[nl * PADH + k] = __float2half(rk[k * GG + g * HH + uu]);
        }
        __syncthreads();
        if ((wid >> 2) == ch) {
            uint32_t ab = base + STAGE_OFF + ((uint32_t)(wid & 3) * 32u + lrow) * ROWB + lcol;
#pragma unroll
            for (int mt = 0; mt < 2; mt++)
#pragma unroll
                for (int kb = 0; kb < 8; kb++)
                    LDSM4(a[mt][kb][0], a[mt][kb][1], a[mt][kb][2], a[mt][kb][3],
                          ab + (uint32_t)mt * 16u * ROWB + (uint32_t)kb * 32u);
        }
    }

    // per-thread x-projection / bias constants (gate order i,f,g,o)
    float kv0 = kern[0 * HH + u_thr], kv1 = kern[1 * HH + u_thr];
    float kv2 = kern[2 * HH + u_thr], kv3 = kern[3 * HH + u_thr];
    float bv0 = bias[0 * HH + u_thr], bv1 = bias[1 * HH + u_thr];
    float bv2 = bias[2 * HH + u_thr], bv3 = bias[3 * HH + u_thr];

    __syncthreads();

    // B-operand lane offset: grp = lane>>3; tiles (k0-7/k8-15) x (bt0/bt0+1)
    const uint32_t grp  = (uint32_t)(lane >> 3);
    const uint32_t bloff = ((uint32_t)(lane & 7) + 8u * (grp & 1)) * ROWB + (grp >> 1) * 16u;
    // h writeback: row u_thr, col bytes bt*16 + 4j
    const uint32_t hwoff = (uint32_t)u_thr * ROWB + 4u * (uint32_t)j;

    float c[32];
#pragma unroll
    for (int i = 0; i < 32; i++) c[i] = 0.0f;

#pragma unroll 1
    for (int t = 0; t < TT; t++) {
        const uint32_t rbuf = base + ((t & 1) ? HT1_OFF : HT0_OFF);
        const uint32_t wbuf = base + ((t & 1) ? HT0_OFF : HT1_OFF);
        const float* xrow = xs + t * 128;

#pragma unroll 1
        for (int btp = 0; btp < 8; btp++) {       // bt0 = 2*btp
            float d[16];
#pragma unroll
            for (int q = 0; q < 16; q++) d[q] = 0.0f;

            if (t > 0) {                           // t==0: h=0 -> d=0
                const uint32_t baddr = rbuf + bloff + (uint32_t)btp * 32u;
#pragma unroll
                for (int kb = 0; kb < 8; kb++) {
                    uint32_t q0, q1, q2, q3;
                    LDSM4T(q0, q1, q2, q3, baddr + (uint32_t)kb * 16u * ROWB);
                    MMA16816(d[0],  d[1],  d[2],  d[3],
                             a[0][kb][0], a[0][kb][1], a[0][kb][2], a[0][kb][3], q0, q1);
                    MMA16816(d[4],  d[5],  d[6],  d[7],
                             a[1][kb][0], a[1][kb][1], a[1][kb][2], a[1][kb][3], q0, q1);
                    MMA16816(d[8],  d[9],  d[10], d[11],
                             a[0][kb][0], a[0][kb][1], a[0][kb][2], a[0][kb][3], q2, q3);
                    MMA16816(d[12], d[13], d[14], d[15],
                             a[1][kb][0], a[1][kb][1], a[1][kb][2], a[1][kb][3], q2, q3);
                }
            }

            // epilogue: sub=0 -> bt=2btp (d[0..7]), sub=1 -> bt=2btp+1 (d[8..15])
#pragma unroll
            for (int sub = 0; sub < 2; sub++) {
                const int bt = 2 * btp + sub;
                const float* dd = d + 8 * sub;
                const float2 x2 = *(const float2*)(xrow + bt * 8 + 2 * j);

                // col p0: i=dd[0] f=dd[2] g=dd[4] o=dd[6]
                float zi = dd[0] + x2.x * kv0 + bv0;
                float zf = dd[2] + x2.x * kv1 + bv1;
                float zg = dd[4] + x2.x * kv2 + bv2;
                float zo = dd[6] + x2.x * kv3 + bv3;
                float ig = sigmoid_f(zi), fg = sigmoid_f(zf), og = sigmoid_f(zo);
                float cn = fmaf(fg, c[2 * bt], ig * fmaxf(zg, 0.0f));
                c[2 * bt] = cn;
                float h0 = og * fmaxf(cn, 0.0f);

                // col p1: dd[1] dd[3] dd[5] dd[7]
                zi = dd[1] + x2.y * kv0 + bv0;
                zf = dd[3] + x2.y * kv1 + bv1;
                zg = dd[5] + x2.y * kv2 + bv2;
                zo = dd[7] + x2.y * kv3 + bv3;
                ig = sigmoid_f(zi); fg = sigmoid_f(zf); og = sigmoid_f(zo);
                float cn2 = fmaf(fg, c[2 * bt + 1], ig * fmaxf(zg, 0.0f));
                c[2 * bt + 1] = cn2;
                float h1 = og * fmaxf(cn2, 0.0f);

                __half2 hp = __floats2half2_rn(h0, h1);
                *(uint32_t*)(smem + (wbuf - base) + hwoff + (uint32_t)bt * 16u) =
                    *(uint32_t*)&hp;
            }
        }
        __syncthreads();   // writes to wbuf visible; reads of rbuf complete
    }

    // ---- output head: y = h_T . Wd + bd  (final h is in buffer 0) ----
    {
        const int b = tid & 127, q = tid >> 7;
        const __half* hcol = (const __half*)(smem + HT0_OFF) + b;
        float s = 0.0f;
#pragma unroll
        for (int uu = 0; uu < 32; uu++) {
            int u = 32 * q + uu;
            s = fmaf(__half2float(hcol[u * PADH]), wdx[u], s);
        }
        red[b * 4 + q] = s;
    }
    __syncthreads();
    if (tid < MTILE) {
        const float* p = red + tid * 4;
        out[b0 + tid] = (p[0] + p[1]) + (p[2] + p[3]) + bd[0];
    }
}

extern "C" void kernel_launch(void* const* d_in, const int* in_sizes, int n_in,
                              void* d_out, int out_size) {
    const float* x    = (const float*)d_in[0];
    const float* kern = (const float*)d_in[1];
    const float* rk   = (const float*)d_in[2];
    const float* bias = (const float*)d_in[3];
    const float* Wd   = (const float*)d_in[4];
    const float* bd   = (const float*)d_in[5];
    float* out = (float*)d_out;

    int B = in_sizes[0] / TT;        // 65536
    int grid = B / MTILE;            // 512

    cudaFuncSetAttribute(lstm_kernel, cudaFuncAttributeMaxDynamicSharedMemorySize, SMEM_TOTAL);
    lstm_kernel<<<grid, NTHREADS, SMEM_TOTAL>>>(x, kern, rk, bias, Wd, bd, out);
}

// round 7
// speedup vs baseline: 1.2228x; 1.2228x over previous
#include <cuda_runtime.h>
#include <cuda_fp16.h>
#include <cstdint>

// ==========================================================================
// LSTM (relu candidate/output) + linear head via mma.sync m16n8k16 fp16
// B=65536, T=12, F=1, H=128.  CTA = 128 batch rows, 512 threads, grid 512.
// R7: warp tile m32 x n128 (4 m-groups x 4 N-quarters) -> B-weight smem
//     traffic halved vs R5 while keeping m-local 128-thread barriers.
//     tanh-sigmoid, fp32 x/bias tables, k-perm contiguous writeback,
//     t=0 MMA skipped (h0=0).
// ==========================================================================

#define TT       12
#define HH       128
#define GG       512
#define MTILE    128
#define NTHREADS 512
#define PADK     136                     // halfs per row (128 data + 8 pad)
#define ROWB     (PADK * 2)              // 272 bytes

// ---- shared memory layout (bytes) ----
#define BT_OFF   0
#define BT_BYTES (GG * ROWB)             // 139264 : R^T fp16 [n_perm][k_perm]
#define A_OFF    (BT_OFF + BT_BYTES)     // h state fp16 [row][k_perm]
#define A_BYTES  (MTILE * ROWB)          // 34816
#define KP_OFF   (A_OFF + A_BYTES)       // float4[128]  kernel per unit (i,f,g,o)
#define BP_OFF   (KP_OFF + 2048)         // float4[128]  bias per unit
#define WD_OFF   (BP_OFF + 2048)         // float[128]
#define XS_OFF   (WD_OFF + 512)          // float[128][12] x staged
#define RED_OFF  (XS_OFF + MTILE*TT*4)   // float[128*16] head partials
#define SMEM_TOTAL (RED_OFF + MTILE*16*4)   // 193024

__device__ __forceinline__ uint32_t s2u(const void* p) {
    uint32_t a;
    asm("{ .reg .u64 t; cvta.to.shared.u64 t, %1; cvt.u32.u64 %0, t; }" : "=r"(a) : "l"(p));
    return a;
}

#define LDSM4(r0, r1, r2, r3, addr) \
    asm volatile("ldmatrix.sync.aligned.m8n8.x4.shared.b16 {%0,%1,%2,%3}, [%4];" \
                 : "=r"(r0), "=r"(r1), "=r"(r2), "=r"(r3) : "r"(addr))

#define MMA16816(d0, d1, d2, d3, a0, a1, a2, a3, b0, b1) \
    asm volatile("mma.sync.aligned.m16n8k16.row.col.f32.f16.f16.f32 " \
                 "{%0,%1,%2,%3}, {%4,%5,%6,%7}, {%8,%9}, {%0,%1,%2,%3};" \
                 : "+f"(d0), "+f"(d1), "+f"(d2), "+f"(d3) \
                 : "r"(a0), "r"(a1), "r"(a2), "r"(a3), "r"(b0), "r"(b1))

// sigmoid(v) = 0.5*tanh(0.5v)+0.5  (single MUFU.TANH)
__device__ __forceinline__ float sigmoid_f(float v) {
    float t;
    asm("tanh.approx.f32 %0, %1;" : "=f"(t) : "f"(0.5f * v));
    return fmaf(0.5f, t, 0.5f);
}

__global__ __launch_bounds__(NTHREADS, 1)
void lstm_kernel(const float* __restrict__ x, const float* __restrict__ kern,
                 const float* __restrict__ rk, const float* __restrict__ bias,
                 const float* __restrict__ Wd, const float* __restrict__ bd,
                 float* __restrict__ out) {
    extern __shared__ char smem[];
    const uint32_t base = s2u(smem);
    const int tid  = threadIdx.x;
    const int lane = tid & 31;
    const int wid  = tid >> 5;
    const int mg   = wid >> 2;       // m-group: 32 rows
    const int Q    = wid & 3;        // N-quarter: 128 perm cols = 32 units
    const int t4   = lane >> 2;      // 0..7
    const int j    = lane & 3;       // 0..3
    const int b0   = blockIdx.x * MTILE;

    __half* bt = (__half*)(smem + BT_OFF);
    float*  kp = (float*)(smem + KP_OFF);
    float*  bp = (float*)(smem + BP_OFF);
    float*  wdx = (float*)(smem + WD_OFF);
    float*  xs = (float*)(smem + XS_OFF);
    float*  red = (float*)(smem + RED_OFF);

    // ---- init: weights -> smem (same verified permutations as R5) ----
    // n-perm: unit u, gate g -> n = 16*(u/4) + 8*(g/2) + 2*(u%4) + (g&1)
    // k-perm: source unit ks -> kk = (ks&3)*32 + (ks>>2)
    for (int i = tid; i < HH * GG; i += NTHREADS) {
        int ks = i >> 9, col = i & 511;
        int u = col & 127, g = col >> 7;
        int n = 16 * (u >> 2) + 8 * (g >> 1) + 2 * (u & 3) + (g & 1);
        int kk = (ks & 3) * 32 + (ks >> 2);
        bt[n * PADK + kk] = __float2half(rk[i]);
    }
    for (int col = tid; col < GG; col += NTHREADS) {
        int u = col & 127, g = col >> 7;
        kp[u * 4 + g] = kern[col];
        bp[u * 4 + g] = bias[col];
    }
    if (tid < HH) wdx[tid] = Wd[tid];
    for (int i = tid; i < MTILE * TT; i += NTHREADS) xs[i] = x[(size_t)b0 * TT + i];
    __syncthreads();

    // ldmatrix lane addressing: row = lane%16, +16B col offset for lanes 16-31
    const uint32_t lrow = (uint32_t)((lane & 7) + (lane & 8));
    const uint32_t lcol = (uint32_t)((lane >> 4) << 4);
    const uint32_t a_base  = base + A_OFF  + (32u * mg + lrow) * ROWB + lcol;
    const uint32_t bt_base = base + BT_OFF + ((uint32_t)Q * 128u + lrow) * ROWB + lcol;

    // rows owned by this thread: r[rr] = 32*mg + 8*rr + t4  (rr = 2*mt + hi)
    const int r0 = 32 * mg + t4;
    // contiguous writeback: unit u=32Q+4pp+j -> kk = j*32 + 8Q + pp
    char* stp[4];
#pragma unroll
    for (int rr = 0; rr < 4; rr++)
        stp[rr] = smem + A_OFF + (r0 + 8 * rr) * ROWB + 64 * j + 16 * Q;

    const float4* kp4 = (const float4*)kp;
    const float4* bp4 = (const float4*)bp;

    float c[32];
#pragma unroll
    for (int i = 0; i < 32; i++) c[i] = 0.0f;
    float ps[4];
#pragma unroll
    for (int i = 0; i < 4; i++) ps[i] = 0.0f;
    const int bid = mg + 1;

#pragma unroll 1
    for (int t = 0; t < TT; t++) {
        asm volatile("bar.sync %0, %1;" :: "r"(bid), "n"(128) : "memory");  // h ready

        uint32_t a[2][8][4];
        if (t > 0) {
#pragma unroll
            for (int mt = 0; mt < 2; mt++)
#pragma unroll
                for (int kb = 0; kb < 8; kb++)
                    LDSM4(a[mt][kb][0], a[mt][kb][1], a[mt][kb][2], a[mt][kb][3],
                          a_base + (uint32_t)mt * 16u * ROWB + (uint32_t)kb * 32u);
        }

        asm volatile("bar.sync %0, %1;" :: "r"(bid), "n"(128) : "memory");  // h consumed

        float xr[4];
#pragma unroll
        for (int rr = 0; rr < 4; rr++) xr[rr] = xs[(r0 + 8 * rr) * TT + t];

        float hp[4];

#pragma unroll 1
        for (int pp = 0; pp < 8; pp++) {
            float d[16];
#pragma unroll
            for (int q = 0; q < 16; q++) d[q] = 0.0f;

            if (t > 0) {
                const uint32_t bta = bt_base + (uint32_t)pp * (16u * ROWB);
#pragma unroll
                for (int kb = 0; kb < 8; kb++) {
                    uint32_t bq0, bq1, bq2, bq3;
                    LDSM4(bq0, bq1, bq2, bq3, bta + (uint32_t)kb * 32u);
                    MMA16816(d[0],  d[1],  d[2],  d[3],
                             a[0][kb][0], a[0][kb][1], a[0][kb][2], a[0][kb][3], bq0, bq2);
                    MMA16816(d[4],  d[5],  d[6],  d[7],
                             a[0][kb][0], a[0][kb][1], a[0][kb][2], a[0][kb][3], bq1, bq3);
                    MMA16816(d[8],  d[9],  d[10], d[11],
                             a[1][kb][0], a[1][kb][1], a[1][kb][2], a[1][kb][3], bq0, bq2);
                    MMA16816(d[12], d[13], d[14], d[15],
                             a[1][kb][0], a[1][kb][1], a[1][kb][2], a[1][kb][3], bq1, bq3);
                }
            }

            const int u = 32 * Q + 4 * pp + j;
            const float4 kv = kp4[u];
            const float4 bv = bp4[u];

            float hh[4];
            // rr=0: mt0 lo (d0,d1 | d4,d5) ; rr=1: mt0 hi (d2,d3 | d6,d7)
            // rr=2: mt1 lo (d8,d9 | d12,d13); rr=3: mt1 hi (d10,d11 | d14,d15)
#pragma unroll
            for (int rr = 0; rr < 4; rr++) {
                const int o = (rr >> 1) * 8 + (rr & 1) * 2;
                float zi = d[o]     + xr[rr] * kv.x + bv.x;
                float zf = d[o + 1] + xr[rr] * kv.y + bv.y;
                float zg = d[o + 4] + xr[rr] * kv.z + bv.z;
                float zo = d[o + 5] + xr[rr] * kv.w + bv.w;
                float ig = sigmoid_f(zi), fg = sigmoid_f(zf), og = sigmoid_f(zo);
                float cn = fmaf(fg, c[4 * pp + rr], ig * fmaxf(zg, 0.0f));
                c[4 * pp + rr] = cn;
                hh[rr] = og * fmaxf(cn, 0.0f);
            }

            if (pp & 1) {
#pragma unroll
                for (int rr = 0; rr < 4; rr++) {
                    __half2 h2 = __floats2half2_rn(hp[rr], hh[rr]);
                    *(uint32_t*)(stp[rr] + 2 * (pp - 1)) = *(uint32_t*)&h2;
                }
            } else {
#pragma unroll
                for (int rr = 0; rr < 4; rr++) hp[rr] = hh[rr];
            }

            if (t == TT - 1) {
                float w = wdx[u];
#pragma unroll
                for (int rr = 0; rr < 4; rr++) ps[rr] = fmaf(hh[rr], w, ps[rr]);
            }
        }
    }

    // ---- output head: y = h_T . Wd + bd ----
#pragma unroll
    for (int rr = 0; rr < 4; rr++)
        red[(r0 + 8 * rr) * 16 + Q * 4 + j] = ps[rr];
    __syncthreads();
    if (tid < MTILE) {
        const float* p = red + tid * 16;
        float s = 0.0f;
#pragma unroll
        for (int i = 0; i < 16; i++) s += p[i];
        out[b0 + tid] = s + bd[0];
    }
}

extern "C" void kernel_launch(void* const* d_in, const int* in_sizes, int n_in,
                              void* d_out, int out_size) {
    const float* x    = (const float*)d_in[0];
    const float* kern = (const float*)d_in[1];
    const float* rk   = (const float*)d_in[2];
    const float* bias = (const float*)d_in[3];
    const float* Wd   = (const float*)d_in[4];
    const float* bd   = (const float*)d_in[5];
    float* out = (float*)d_out;

    int B = in_sizes[0] / TT;        // 65536
    int grid = B / MTILE;            // 512

    cudaFuncSetAttribute(lstm_kernel, cudaFuncAttributeMaxDynamicSharedMemorySize, SMEM_TOTAL);
    lstm_kernel<<<grid, NTHREADS, SMEM_TOTAL>>>(x, kern, rk, bias, Wd, bd, out);
}

// round 8
// speedup vs baseline: 1.3602x; 1.1124x over previous
#include <cuda_runtime.h>
#include <cuda_fp16.h>
#include <cstdint>

// ==========================================================================
// LSTM (relu candidate/output) + linear head via mma.sync m16n8k16 fp16
// B=65536, T=12, F=1, H=128.
// R8: persistent CTAs (grid 148, weights staged once), double-buffered h
//     (one 128-thread barrier per step), head hoisted out of the hot loop.
//     Core MMA/epilogue identical to R7 (397us, rel_err 2.9e-5).
// ==========================================================================

#define TT       12
#define HH       128
#define GG       512
#define MTILE    128
#define NTHREADS 512
#define NTILES   512                     // 65536 / 128
#define GRID     148
#define PADK     136                     // halfs per row (128 data + 8 pad)
#define ROWB     (PADK * 2)              // 272 bytes

// ---- shared memory layout (bytes) ----
#define BT_OFF   0
#define BT_BYTES (GG * ROWB)             // 139264 : R^T fp16 [n_perm][k_perm]
#define A0_OFF   (BT_OFF + BT_BYTES)     // h buffers fp16 [row][k_perm]
#define A_BYTES  (MTILE * ROWB)          // 34816
#define A1_OFF   (A0_OFF + A_BYTES)
#define KP_OFF   (A1_OFF + A_BYTES)      // float4[128] kernel per unit
#define BP_OFF   (KP_OFF + 2048)         // float4[128] bias per unit
#define WDP_OFF  (BP_OFF + 2048)         // float[128] Wd permuted by kk
#define XS_OFF   (WDP_OFF + 512)         // float[128][12] x staged
#define RED_OFF  (XS_OFF + MTILE*TT*4)   // float[128*4] head partials
#define SMEM_TOTAL (RED_OFF + MTILE*4*4) // 221696

__device__ __forceinline__ uint32_t s2u(const void* p) {
    uint32_t a;
    asm("{ .reg .u64 t; cvta.to.shared.u64 t, %1; cvt.u32.u64 %0, t; }" : "=r"(a) : "l"(p));
    return a;
}

#define LDSM4(r0, r1, r2, r3, addr) \
    asm volatile("ldmatrix.sync.aligned.m8n8.x4.shared.b16 {%0,%1,%2,%3}, [%4];" \
                 : "=r"(r0), "=r"(r1), "=r"(r2), "=r"(r3) : "r"(addr))

#define MMA16816(d0, d1, d2, d3, a0, a1, a2, a3, b0, b1) \
    asm volatile("mma.sync.aligned.m16n8k16.row.col.f32.f16.f16.f32 " \
                 "{%0,%1,%2,%3}, {%4,%5,%6,%7}, {%8,%9}, {%0,%1,%2,%3};" \
                 : "+f"(d0), "+f"(d1), "+f"(d2), "+f"(d3) \
                 : "r"(a0), "r"(a1), "r"(a2), "r"(a3), "r"(b0), "r"(b1))

// sigmoid(v) = 0.5*tanh(0.5v)+0.5  (single MUFU.TANH)
__device__ __forceinline__ float sigmoid_f(float v) {
    float t;
    asm("tanh.approx.f32 %0, %1;" : "=f"(t) : "f"(0.5f * v));
    return fmaf(0.5f, t, 0.5f);
}

__global__ __launch_bounds__(NTHREADS, 1)
void lstm_kernel(const float* __restrict__ x, const float* __restrict__ kern,
                 const float* __restrict__ rk, const float* __restrict__ bias,
                 const float* __restrict__ Wd, const float* __restrict__ bd,
                 float* __restrict__ out) {
    extern __shared__ char smem[];
    const uint32_t base = s2u(smem);
    const int tid  = threadIdx.x;
    const int lane = tid & 31;
    const int wid  = tid >> 5;
    const int mg   = wid >> 2;       // m-group: 32 rows
    const int Q    = wid & 3;        // N-quarter: 128 perm cols = 32 units
    const int t4   = lane >> 2;      // 0..7
    const int j    = lane & 3;       // 0..3

    __half* bt  = (__half*)(smem + BT_OFF);
    float*  kp  = (float*)(smem + KP_OFF);
    float*  bp  = (float*)(smem + BP_OFF);
    float*  wdp = (float*)(smem + WDP_OFF);
    float*  xs  = (float*)(smem + XS_OFF);
    float*  red = (float*)(smem + RED_OFF);

    // ---- one-time init: weights -> smem (verified R5/R7 permutations) ----
    // n-perm: unit u, gate g -> n = 16*(u/4) + 8*(g/2) + 2*(u%4) + (g&1)
    // k-perm: source unit ks -> kk = (ks&3)*32 + (ks>>2)
    for (int i = tid; i < HH * GG; i += NTHREADS) {
        int ks = i >> 9, col = i & 511;
        int u = col & 127, g = col >> 7;
        int n = 16 * (u >> 2) + 8 * (g >> 1) + 2 * (u & 3) + (g & 1);
        int kk = (ks & 3) * 32 + (ks >> 2);
        bt[n * PADK + kk] = __float2half(rk[i]);
    }
    for (int col = tid; col < GG; col += NTHREADS) {
        int u = col & 127, g = col >> 7;
        kp[u * 4 + g] = kern[col];
        bp[u * 4 + g] = bias[col];
    }
    if (tid < HH) {
        // head weight permuted to storage index kk(u) = (u&3)*32 + (u>>2)
        int kk = (tid & 3) * 32 + (tid >> 2);
        wdp[kk] = Wd[tid];
    }

    // ldmatrix lane addressing: row = lane%16, +16B col offset for lanes 16-31
    const uint32_t lrow = (uint32_t)((lane & 7) + (lane & 8));
    const uint32_t lcol = (uint32_t)((lane >> 4) << 4);
    const uint32_t a_rel  = (32u * mg + lrow) * ROWB + lcol;  // + buf base
    const uint32_t bt_base = base + BT_OFF + ((uint32_t)Q * 128u + lrow) * ROWB + lcol;

    const int r0 = 32 * mg + t4;
    // contiguous writeback offsets (relative to buffer base):
    // unit u=32Q+4pp+j -> half index j*32 + 8Q + pp
    uint32_t st_rel[4];
#pragma unroll
    for (int rr = 0; rr < 4; rr++)
        st_rel[rr] = (uint32_t)((r0 + 8 * rr) * ROWB + 64 * j + 16 * Q);

    const float4* kp4 = (const float4*)kp;
    const float4* bp4 = (const float4*)bp;
    const int bid = mg + 1;

    // ---- persistent tile loop ----
    for (int tile = blockIdx.x; tile < NTILES; tile += GRID) {
        const int b0 = tile * MTILE;

        // stage x for this tile (coalesced)
        for (int i = tid; i < MTILE * TT; i += NTHREADS) xs[i] = x[(size_t)b0 * TT + i];
        __syncthreads();   // x ready; also fences previous tile's head reads

        float c[32];
#pragma unroll
        for (int i = 0; i < 32; i++) c[i] = 0.0f;

#pragma unroll 1
        for (int t = 0; t < TT; t++) {
            // one barrier/step: h(t-1) writes (to buf[t&1]) are visible
            asm volatile("bar.sync %0, %1;" :: "r"(bid), "n"(128) : "memory");

            const uint32_t rbase = base + ((t & 1) ? A1_OFF : A0_OFF);
            char* wbase = smem + ((t & 1) ? A0_OFF : A1_OFF);

            uint32_t a[2][8][4];
            if (t > 0) {
#pragma unroll
                for (int mt = 0; mt < 2; mt++)
#pragma unroll
                    for (int kb = 0; kb < 8; kb++)
                        LDSM4(a[mt][kb][0], a[mt][kb][1], a[mt][kb][2], a[mt][kb][3],
                              rbase + a_rel + (uint32_t)mt * 16u * ROWB + (uint32_t)kb * 32u);
            }

            float xr[4];
#pragma unroll
            for (int rr = 0; rr < 4; rr++) xr[rr] = xs[(r0 + 8 * rr) * TT + t];

            float hp[4];

#pragma unroll 1
            for (int pp = 0; pp < 8; pp++) {
                float d[16];
#pragma unroll
                for (int q = 0; q < 16; q++) d[q] = 0.0f;

                if (t > 0) {
                    const uint32_t bta = bt_base + (uint32_t)pp * (16u * ROWB);
#pragma unroll
                    for (int kb = 0; kb < 8; kb++) {
                        uint32_t bq0, bq1, bq2, bq3;
                        LDSM4(bq0, bq1, bq2, bq3, bta + (uint32_t)kb * 32u);
                        MMA16816(d[0],  d[1],  d[2],  d[3],
                                 a[0][kb][0], a[0][kb][1], a[0][kb][2], a[0][kb][3], bq0, bq2);
                        MMA16816(d[4],  d[5],  d[6],  d[7],
                                 a[0][kb][0], a[0][kb][1], a[0][kb][2], a[0][kb][3], bq1, bq3);
                        MMA16816(d[8],  d[9],  d[10], d[11],
                                 a[1][kb][0], a[1][kb][1], a[1][kb][2], a[1][kb][3], bq0, bq2);
                        MMA16816(d[12], d[13], d[14], d[15],
                                 a[1][kb][0], a[1][kb][1], a[1][kb][2], a[1][kb][3], bq1, bq3);
                    }
                }

                const int u = 32 * Q + 4 * pp + j;
                const float4 kv = kp4[u];
                const float4 bv = bp4[u];

                float hh[4];
#pragma unroll
                for (int rr = 0; rr < 4; rr++) {
                    const int o = (rr >> 1) * 8 + (rr & 1) * 2;
                    float zi = d[o]     + xr[rr] * kv.x + bv.x;
                    float zf = d[o + 1] + xr[rr] * kv.y + bv.y;
                    float zg = d[o + 4] + xr[rr] * kv.z + bv.z;
                    float zo = d[o + 5] + xr[rr] * kv.w + bv.w;
                    float ig = sigmoid_f(zi), fg = sigmoid_f(zf), og = sigmoid_f(zo);
                    float cn = fmaf(fg, c[4 * pp + rr], ig * fmaxf(zg, 0.0f));
                    c[4 * pp + rr] = cn;
                    hh[rr] = og * fmaxf(cn, 0.0f);
                }

                if (pp & 1) {
#pragma unroll
                    for (int rr = 0; rr < 4; rr++) {
                        __half2 h2 = __floats2half2_rn(hp[rr], hh[rr]);
                        *(uint32_t*)(wbase + st_rel[rr] + 2 * (pp - 1)) = *(uint32_t*)&h2;
                    }
                } else {
#pragma unroll
                    for (int rr = 0; rr < 4; rr++) hp[rr] = hh[rr];
                }
            }
        }

        // ---- head: final h is in buf0 (written at t=11).  y = h.Wd + bd ----
        __syncthreads();   // all groups' final h visible CTA-wide
        {
            const int row = tid >> 2, q = tid & 3;
            const __half* hrow = (const __half*)(smem + A0_OFF) + row * PADK + 32 * q;
            const float*  wq   = wdp + 32 * q;
            float s = 0.0f;
#pragma unroll
            for (int i = 0; i < 32; i += 2) {
                float2 hv = __half22float2(*(const __half2*)(hrow + i));
                s = fmaf(hv.x, wq[i], s);
                s = fmaf(hv.y, wq[i + 1], s);
            }
            red[row * 4 + q] = s;
        }
        __syncthreads();
        if (tid < MTILE) {
            const float* p = red + tid * 4;
            out[b0 + tid] = (p[0] + p[1]) + (p[2] + p[3]) + bd[0];
        }
    }
}

extern "C" void kernel_launch(void* const* d_in, const int* in_sizes, int n_in,
                              void* d_out, int out_size) {
    const float* x    = (const float*)d_in[0];
    const float* kern = (const float*)d_in[1];
    const float* rk   = (const float*)d_in[2];
    const float* bias = (const float*)d_in[3];
    const float* Wd   = (const float*)d_in[4];
    const float* bd   = (const float*)d_in[5];
    float* out = (float*)d_out;

    cudaFuncSetAttribute(lstm_kernel, cudaFuncAttributeMaxDynamicSharedMemorySize, SMEM_TOTAL);
    lstm_kernel<<<GRID, NTHREADS, SMEM_TOTAL>>>(x, kern, rk, bias, Wd, bd, out);
}

// round 9
// speedup vs baseline: 1.4071x; 1.0345x over previous
#include <cuda_runtime.h>
#include <cuda_fp16.h>
#include <cstdint>

// ==========================================================================
// LSTM (relu candidate/output) + linear head via mma.sync m16n8k16 fp16
// B=65536, T=12, F=1, H=128.
// R9: MTILE=64 (1024 tiles -> 98.8% persistent-wave balance, c regs 32->16),
//     0.5-prescaled i/f/o weights (sigmoid = tanh+fma, exact), t=0 peeled,
//     STS.64 h writeback. Core MMA mapping identical to R7/R8.
// ==========================================================================

#define TT       12
#define HH       128
#define GG       512
#define MTILE    64
#define NTHREADS 512
#define NTILES   1024                    // 65536 / 64
#define GRID     148
#define PADK     136                     // halfs per row (128 data + 8 pad)
#define ROWB     (PADK * 2)              // 272 bytes

// ---- shared memory layout (bytes) ----
#define BT_OFF   0
#define BT_BYTES (GG * ROWB)             // 139264 : R^T fp16 [n_perm][k_perm], i/f/o rows x0.5
#define A0_OFF   (BT_OFF + BT_BYTES)     // h buffers fp16 [row][k_perm]
#define A_BYTES  (MTILE * ROWB)          // 17408
#define A1_OFF   (A0_OFF + A_BYTES)
#define KP_OFF   (A1_OFF + A_BYTES)      // float4[128] kernel per unit (i/f/o x0.5)
#define BP_OFF   (KP_OFF + 2048)         // float4[128] bias per unit (i/f/o x0.5)
#define WDP_OFF  (BP_OFF + 2048)         // float[128] Wd permuted by kk
#define XS_OFF   (WDP_OFF + 512)         // float[64][12] x staged
#define RED_OFF  (XS_OFF + MTILE*TT*4)   // float[64*4] head partials
#define SMEM_TOTAL (RED_OFF + MTILE*4*4) // 182784

__device__ __forceinline__ uint32_t s2u(const void* p) {
    uint32_t a;
    asm("{ .reg .u64 t; cvta.to.shared.u64 t, %1; cvt.u32.u64 %0, t; }" : "=r"(a) : "l"(p));
    return a;
}

#define LDSM4(r0, r1, r2, r3, addr) \
    asm volatile("ldmatrix.sync.aligned.m8n8.x4.shared.b16 {%0,%1,%2,%3}, [%4];" \
                 : "=r"(r0), "=r"(r1), "=r"(r2), "=r"(r3) : "r"(addr))

#define MMA16816(d0, d1, d2, d3, a0, a1, a2, a3, b0, b1) \
    asm volatile("mma.sync.aligned.m16n8k16.row.col.f32.f16.f16.f32 " \
                 "{%0,%1,%2,%3}, {%4,%5,%6,%7}, {%8,%9}, {%0,%1,%2,%3};" \
                 : "+f"(d0), "+f"(d1), "+f"(d2), "+f"(d3) \
                 : "r"(a0), "r"(a1), "r"(a2), "r"(a3), "r"(b0), "r"(b1))

// Input v is PRE-HALVED (weights for i/f/o scaled 0.5): sigmoid = 0.5*tanh(v)+0.5
__device__ __forceinline__ float sigmoid_pre(float v) {
    float t;
    asm("tanh.approx.f32 %0, %1;" : "=f"(t) : "f"(v));
    return fmaf(0.5f, t, 0.5f);
}

__global__ __launch_bounds__(NTHREADS, 1)
void lstm_kernel(const float* __restrict__ x, const float* __restrict__ kern,
                 const float* __restrict__ rk, const float* __restrict__ bias,
                 const float* __restrict__ Wd, const float* __restrict__ bd,
                 float* __restrict__ out) {
    extern __shared__ char smem[];
    const uint32_t base = s2u(smem);
    const int tid  = threadIdx.x;
    const int lane = tid & 31;
    const int wid  = tid >> 5;
    const int mg   = wid >> 3;       // m-group: 32 rows (0..1)
    const int Q    = wid & 7;        // N-eighth: 64 perm cols = 16 units (0..7)
    const int t4   = lane >> 2;      // 0..7
    const int j    = lane & 3;       // 0..3

    __half* bt  = (__half*)(smem + BT_OFF);
    float*  kp  = (float*)(smem + KP_OFF);
    float*  bp  = (float*)(smem + BP_OFF);
    float*  wdp = (float*)(smem + WDP_OFF);
    float*  xs  = (float*)(smem + XS_OFF);
    float*  red = (float*)(smem + RED_OFF);

    // ---- one-time init (verified R5/R7 permutations + 0.5 prescale) ----
    // n-perm: unit u, gate g -> n = 16*(u/4) + 8*(g/2) + 2*(u%4) + (g&1)
    // k-perm: source unit ks -> kk = (ks&3)*32 + (ks>>2)
    // gates g: 0=i 1=f 2=candidate 3=o; i/f/o scaled by 0.5 (exact in fp16)
    for (int i = tid; i < HH * GG; i += NTHREADS) {
        int ks = i >> 9, col = i & 511;
        int u = col & 127, g = col >> 7;
        int n = 16 * (u >> 2) + 8 * (g >> 1) + 2 * (u & 3) + (g & 1);
        int kk = (ks & 3) * 32 + (ks >> 2);
        float sc = (g == 2) ? 1.0f : 0.5f;
        bt[n * PADK + kk] = __float2half(rk[i] * sc);
    }
    for (int col = tid; col < GG; col += NTHREADS) {
        int u = col & 127, g = col >> 7;
        float sc = (g == 2) ? 1.0f : 0.5f;
        kp[u * 4 + g] = kern[col] * sc;
        bp[u * 4 + g] = bias[col] * sc;
    }
    if (tid < HH) {
        int kk = (tid & 3) * 32 + (tid >> 2);
        wdp[kk] = Wd[tid];
    }

    // ldmatrix lane addressing: row = lane%16, +16B col offset for lanes 16-31
    const uint32_t lrow = (uint32_t)((lane & 7) + (lane & 8));
    const uint32_t lcol = (uint32_t)((lane >> 4) << 4);
    const uint32_t a_rel   = (32u * mg + lrow) * ROWB + lcol;  // + buf base
    const uint32_t bt_base = base + BT_OFF + ((uint32_t)Q * 64u + lrow) * ROWB + lcol;

    const int r0 = 32 * mg + t4;
    // writeback: unit u=16Q+4pp+j -> kk = 32j + 4Q + pp; 4 halfs per (j,Q) window
    uint32_t st_rel[4];
#pragma unroll
    for (int rr = 0; rr < 4; rr++)
        st_rel[rr] = (uint32_t)((r0 + 8 * rr) * ROWB + 64 * j + 8 * Q);

    const float4* kp4 = (const float4*)kp;
    const float4* bp4 = (const float4*)bp;
    const int bid = mg + 1;

    // ---- persistent tile loop ----
    for (int tile = blockIdx.x; tile < NTILES; tile += GRID) {
        const int b0 = tile * MTILE;

        for (int i = tid; i < MTILE * TT; i += NTHREADS) xs[i] = x[(size_t)b0 * TT + i];
        __syncthreads();   // x ready; also fences previous tile's smem reads

        float c[16];
        float xr[4];
#pragma unroll
        for (int rr = 0; rr < 4; rr++) xr[rr] = xs[(r0 + 8 * rr) * TT + 0];

        // ---- t = 0 peeled: h0 = 0 -> z = x*k + b only; writes buf A1 ----
        {
            uint32_t hw[4][2];
#pragma unroll
            for (int pp = 0; pp < 4; pp++) {
                const int u = 16 * Q + 4 * pp + j;
                const float4 kv = kp4[u];
                const float4 bv = bp4[u];
                float hp[4];
#pragma unroll
                for (int rr = 0; rr < 4; rr++) {
                    float zi = xr[rr] * kv.x + bv.x;
                    float zf = xr[rr] * kv.y + bv.y;   (void)zf;
                    float zg = xr[rr] * kv.z + bv.z;
                    float zo = xr[rr] * kv.w + bv.w;
                    float ig = sigmoid_pre(zi), og = sigmoid_pre(zo);
                    float cn = ig * fmaxf(zg, 0.0f);   // f*c0 = 0
                    c[4 * pp + rr] = cn;
                    hp[rr] = og * fmaxf(cn, 0.0f);
                }
                if (pp & 1) {
#pragma unroll
                    for (int rr = 0; rr < 4; rr++) {
                        // pair with previous pp via shared hprev storage
                    }
                }
                // stash h into hw pairs: even pp -> lo half, odd pp -> hi half
                if ((pp & 1) == 0) {
#pragma unroll
                    for (int rr = 0; rr < 4; rr++) {
                        __half2 h2 = __floats2half2_rn(hp[rr], 0.0f);
                        hw[rr][pp >> 1] = *(uint32_t*)&h2;
                    }
                } else {
#pragma unroll
                    for (int rr = 0; rr < 4; rr++) {
                        __half2 h2; *(uint32_t*)&h2 = hw[rr][pp >> 1];
                        h2.y = __float2half(hp[rr]);
                        hw[rr][pp >> 1] = *(uint32_t*)&h2;
                    }
                }
            }
#pragma unroll
            for (int rr = 0; rr < 4; rr++)
                *(uint2*)(smem + A1_OFF + st_rel[rr]) = make_uint2(hw[rr][0], hw[rr][1]);
        }

        // ---- t = 1..11 (branchless) ----
#pragma unroll 1
        for (int t = 1; t < TT; t++) {
            asm volatile("bar.sync %0, %1;" :: "r"(bid), "n"(256) : "memory");

            const uint32_t rbase = base + ((t & 1) ? A1_OFF : A0_OFF);
            char* wbase = smem + ((t & 1) ? A0_OFF : A1_OFF);

            uint32_t a[2][8][4];
#pragma unroll
            for (int mt = 0; mt < 2; mt++)
#pragma unroll
                for (int kb = 0; kb < 8; kb++)
                    LDSM4(a[mt][kb][0], a[mt][kb][1], a[mt][kb][2], a[mt][kb][3],
                          rbase + a_rel + (uint32_t)mt * 16u * ROWB + (uint32_t)kb * 32u);

#pragma unroll
            for (int rr = 0; rr < 4; rr++) xr[rr] = xs[(r0 + 8 * rr) * TT + t];

            uint32_t hw[4][2];

#pragma unroll 1
            for (int pp = 0; pp < 4; pp++) {
                float d[16];
#pragma unroll
                for (int q = 0; q < 16; q++) d[q] = 0.0f;

                const uint32_t bta = bt_base + (uint32_t)pp * (16u * ROWB);
#pragma unroll
                for (int kb = 0; kb < 8; kb++) {
                    uint32_t bq0, bq1, bq2, bq3;
                    LDSM4(bq0, bq1, bq2, bq3, bta + (uint32_t)kb * 32u);
                    MMA16816(d[0],  d[1],  d[2],  d[3],
                             a[0][kb][0], a[0][kb][1], a[0][kb][2], a[0][kb][3], bq0, bq2);
                    MMA16816(d[4],  d[5],  d[6],  d[7],
                             a[0][kb][0], a[0][kb][1], a[0][kb][2], a[0][kb][3], bq1, bq3);
                    MMA16816(d[8],  d[9],  d[10], d[11],
                             a[1][kb][0], a[1][kb][1], a[1][kb][2], a[1][kb][3], bq0, bq2);
                    MMA16816(d[12], d[13], d[14], d[15],
                             a[1][kb][0], a[1][kb][1], a[1][kb][2], a[1][kb][3], bq1, bq3);
                }

                const int u = 16 * Q + 4 * pp + j;
                const float4 kv = kp4[u];
                const float4 bv = bp4[u];

                float hp[4];
                // rr=0: mt0 lo (d0,d1 | d4,d5); rr=1: mt0 hi; rr=2/3: mt1
#pragma unroll
                for (int rr = 0; rr < 4; rr++) {
                    const int o = (rr >> 1) * 8 + (rr & 1) * 2;
                    float zi = d[o]     + xr[rr] * kv.x + bv.x;   // pre-halved
                    float zf = d[o + 1] + xr[rr] * kv.y + bv.y;   // pre-halved
                    float zg = d[o + 4] + xr[rr] * kv.z + bv.z;   // full scale
                    float zo = d[o + 5] + xr[rr] * kv.w + bv.w;   // pre-halved
                    float ig = sigmoid_pre(zi), fg = sigmoid_pre(zf), og = sigmoid_pre(zo);
                    float cn = fmaf(fg, c[4 * pp + rr], ig * fmaxf(zg, 0.0f));
                    c[4 * pp + rr] = cn;
                    hp[rr] = og * fmaxf(cn, 0.0f);
                }

                if ((pp & 1) == 0) {
#pragma unroll
                    for (int rr = 0; rr < 4; rr++) {
                        __half2 h2 = __floats2half2_rn(hp[rr], 0.0f);
                        hw[rr][pp >> 1] = *(uint32_t*)&h2;
                    }
                } else {
#pragma unroll
                    for (int rr = 0; rr < 4; rr++) {
                        __half2 h2; *(uint32_t*)&h2 = hw[rr][pp >> 1];
                        h2.y = __float2half(hp[rr]);
                        hw[rr][pp >> 1] = *(uint32_t*)&h2;
                    }
                }
            }

#pragma unroll
            for (int rr = 0; rr < 4; rr++)
                *(uint2*)(wbase + st_rel[rr]) = make_uint2(hw[rr][0], hw[rr][1]);
        }

        // ---- head: final h in buf A0 (t=11 writes A0).  y = h.Wd + bd ----
        __syncthreads();
        if (tid < MTILE * 4) {
            const int row = tid >> 2, q = tid & 3;
            const __half* hrow = (const __half*)(smem + A0_OFF) + row * PADK + 32 * q;
            const float*  wq   = wdp + 32 * q;
            float s = 0.0f;
#pragma unroll
            for (int i = 0; i < 32; i += 2) {
                float2 hv = __half22float2(*(const __half2*)(hrow + i));
                s = fmaf(hv.x, wq[i], s);
                s = fmaf(hv.y, wq[i + 1], s);
            }
            red[row * 4 + q] = s;
        }
        __syncthreads();
        if (tid < MTILE) {
            const float* p = red + tid * 4;
            out[b0 + tid] = (p[0] + p[1]) + (p[2] + p[3]) + bd[0];
        }
    }
}

extern "C" void kernel_launch(void* const* d_in, const int* in_sizes, int n_in,
                              void* d_out, int out_size) {
    const float* x    = (const float*)d_in[0];
    const float* kern = (const float*)d_in[1];
    const float* rk   = (const float*)d_in[2];
    const float* bias = (const float*)d_in[3];
    const float* Wd   = (const float*)d_in[4];
    const float* bd   = (const float*)d_in[5];
    float* out = (float*)d_out;

    cudaFuncSetAttribute(lstm_kernel, cudaFuncAttributeMaxDynamicSharedMemorySize, SMEM_TOTAL);
    lstm_kernel<<<GRID, NTHREADS, SMEM_TOTAL>>>(x, kern, rk, bias, Wd, bd, out);
}

// round 10
// speedup vs baseline: 1.4734x; 1.0471x over previous
#include <cuda_runtime.h>
#include <cuda_fp16.h>
#include <cstdint>

// ==========================================================================
// LSTM (relu candidate/output) + linear head via mma.sync m16n8k16 fp16
// B=65536, T=12, F=1, H=128.
// R10: two fully independent 256-thread pipelines per CTA (own 32-row tile
//      stream, own barriers -> anti-phased pipe usage), MMA accumulators
//      seeded with x*k+bias (epilogue FADDs eliminated), pp unroll 2.
//      Weight permutations / MMA mapping identical to R7-R9.
// ==========================================================================

#define TT       12
#define HH       128
#define GG       512
#define GTILE    32                      // rows per group tile
#define NTHREADS 512
#define NGT      2048                    // 65536 / 32
#define GRID     148
#define NGROUPS  (GRID * 2)              // 296
#define PADK     136                     // halfs per row (128 data + 8 pad)
#define ROWB     (PADK * 2)              // 272 bytes

// ---- shared memory layout (bytes) ----
#define BT_OFF    0
#define BT_BYTES  (GG * ROWB)            // 139264 : R^T fp16, i/f/o rows x0.5
#define A_BASE    (BT_OFF + BT_BYTES)    // 4 h buffers: [g][buf] 32x272
#define AG_BYTES  (GTILE * ROWB)         // 8704
#define KP_OFF    (A_BASE + 4 * AG_BYTES)        // float4[128] kernel (i/f/o x0.5)
#define BP_OFF    (KP_OFF + 2048)                // float4[128] bias (i/f/o x0.5)
#define WDP_OFF   (BP_OFF + 2048)                // float[128] Wd permuted by kk
#define XS_BASE   (WDP_OFF + 512)                // float[2][32*12]
#define RED_BASE  (XS_BASE + 2 * GTILE * TT * 4) // float[2][32*8]
#define SMEM_TOTAL (RED_BASE + 2 * GTILE * 8 * 4)

__device__ __forceinline__ uint32_t s2u(const void* p) {
    uint32_t a;
    asm("{ .reg .u64 t; cvta.to.shared.u64 t, %1; cvt.u32.u64 %0, t; }" : "=r"(a) : "l"(p));
    return a;
}

#define LDSM4(r0, r1, r2, r3, addr) \
    asm volatile("ldmatrix.sync.aligned.m8n8.x4.shared.b16 {%0,%1,%2,%3}, [%4];" \
                 : "=r"(r0), "=r"(r1), "=r"(r2), "=r"(r3) : "r"(addr))

#define MMA16816(d0, d1, d2, d3, a0, a1, a2, a3, b0, b1) \
    asm volatile("mma.sync.aligned.m16n8k16.row.col.f32.f16.f16.f32 " \
                 "{%0,%1,%2,%3}, {%4,%5,%6,%7}, {%8,%9}, {%0,%1,%2,%3};" \
                 : "+f"(d0), "+f"(d1), "+f"(d2), "+f"(d3) \
                 : "r"(a0), "r"(a1), "r"(a2), "r"(a3), "r"(b0), "r"(b1))

// Input v is PRE-HALVED (i/f/o weights scaled 0.5): sigmoid = 0.5*tanh(v)+0.5
__device__ __forceinline__ float sigmoid_pre(float v) {
    float t;
    asm("tanh.approx.f32 %0, %1;" : "=f"(t) : "f"(v));
    return fmaf(0.5f, t, 0.5f);
}

__global__ __launch_bounds__(NTHREADS, 1)
void lstm_kernel(const float* __restrict__ x, const float* __restrict__ kern,
                 const float* __restrict__ rk, const float* __restrict__ bias,
                 const float* __restrict__ Wd, const float* __restrict__ bd,
                 float* __restrict__ out) {
    extern __shared__ char smem[];
    const uint32_t base = s2u(smem);
    const int tid  = threadIdx.x;
    const int lane = tid & 31;
    const int wid  = tid >> 5;
    const int g    = wid >> 3;       // pipeline group 0/1 (8 warps each)
    const int Q    = wid & 7;        // N-eighth: 64 perm cols = 16 units
    const int wtid = tid & 255;      // thread id within group
    const int t4   = lane >> 2;
    const int j    = lane & 3;

    __half* bt  = (__half*)(smem + BT_OFF);
    float*  kp  = (float*)(smem + KP_OFF);
    float*  bp  = (float*)(smem + BP_OFF);
    float*  wdp = (float*)(smem + WDP_OFF);
    float*  xsg = (float*)(smem + XS_BASE + g * (GTILE * TT * 4));
    float*  redg = (float*)(smem + RED_BASE + g * (GTILE * 8 * 4));

    // ---- one-time init (verified permutations + exact 0.5 prescale) ----
    // n-perm: unit u, gate gt -> n = 16*(u/4) + 8*(gt/2) + 2*(u%4) + (gt&1)
    // k-perm: source unit ks -> kk = (ks&3)*32 + (ks>>2)
    // gates gt: 0=i 1=f 2=candidate 3=o ; i/f/o scaled by 0.5
    for (int i = tid; i < HH * GG; i += NTHREADS) {
        int ks = i >> 9, col = i & 511;
        int u = col & 127, gt = col >> 7;
        int n = 16 * (u >> 2) + 8 * (gt >> 1) + 2 * (u & 3) + (gt & 1);
        int kk = (ks & 3) * 32 + (ks >> 2);
        float sc = (gt == 2) ? 1.0f : 0.5f;
        bt[n * PADK + kk] = __float2half(rk[i] * sc);
    }
    for (int col = tid; col < GG; col += NTHREADS) {
        int u = col & 127, gt = col >> 7;
        float sc = (gt == 2) ? 1.0f : 0.5f;
        kp[u * 4 + gt] = kern[col] * sc;
        bp[u * 4 + gt] = bias[col] * sc;
    }
    if (tid < HH) {
        int kk = (tid & 3) * 32 + (tid >> 2);
        wdp[kk] = Wd[tid];
    }
    __syncthreads();   // ONLY CTA-wide sync; groups free-run afterwards

    // group h buffers
    const uint32_t ag0 = base + A_BASE + (uint32_t)g * 2u * AG_BYTES;      // buf0
    const uint32_t ag1 = ag0 + AG_BYTES;                                    // buf1

    // ldmatrix lane addressing
    const uint32_t lrow = (uint32_t)((lane & 7) + (lane & 8));
    const uint32_t lcol = (uint32_t)((lane >> 4) << 4);
    const uint32_t a_rel   = lrow * ROWB + lcol;
    const uint32_t bt_base = base + BT_OFF + ((uint32_t)Q * 64u + lrow) * ROWB + lcol;

    const int r0 = t4;               // rows r0+8rr, rr=0..3
    uint32_t st_rel[4];
#pragma unroll
    for (int rr = 0; rr < 4; rr++)
        st_rel[rr] = (uint32_t)((r0 + 8 * rr) * ROWB + 64 * j + 8 * Q);

    const float4* kp4 = (const float4*)kp;
    const float4* bp4 = (const float4*)bp;
    const int bid = g + 1;

    // ---- persistent per-group tile loop ----
    for (int tile = blockIdx.x * 2 + g; tile < NGT; tile += NGROUPS) {
        const int b0 = tile * GTILE;

        for (int i = wtid; i < GTILE * TT; i += 256) xsg[i] = x[(size_t)b0 * TT + i];
        asm volatile("bar.sync %0, %1;" :: "r"(bid), "n"(256) : "memory");  // xs ready

        float c[16];
        float xr[4];
#pragma unroll
        for (int rr = 0; rr < 4; rr++) xr[rr] = xsg[(r0 + 8 * rr) * TT + 0];

        // ---- t = 0 peeled (h0=0): z = x*k + b ; writes buf1 ----
        {
            uint32_t hw[4][2];
#pragma unroll
            for (int pp = 0; pp < 4; pp++) {
                const int u = 16 * Q + 4 * pp + j;
                const float4 kv = kp4[u];
                const float4 bv = bp4[u];
#pragma unroll
                for (int rr = 0; rr < 4; rr++) {
                    float zi = fmaf(xr[rr], kv.x, bv.x);
                    float zg = fmaf(xr[rr], kv.z, bv.z);
                    float zo = fmaf(xr[rr], kv.w, bv.w);
                    float ig = sigmoid_pre(zi), og = sigmoid_pre(zo);
                    float cn = ig * fmaxf(zg, 0.0f);
                    c[4 * pp + rr] = cn;
                    float hv = og * fmaxf(cn, 0.0f);
                    if ((pp & 1) == 0) {
                        __half2 h2 = __floats2half2_rn(hv, 0.0f);
                        hw[rr][pp >> 1] = *(uint32_t*)&h2;
                    } else {
                        __half2 h2; *(uint32_t*)&h2 = hw[rr][pp >> 1];
                        h2.y = __float2half(hv);
                        hw[rr][pp >> 1] = *(uint32_t*)&h2;
                    }
                }
            }
#pragma unroll
            for (int rr = 0; rr < 4; rr++)
                *(uint2*)(smem + (ag1 - base) + st_rel[rr]) = make_uint2(hw[rr][0], hw[rr][1]);
        }

        // ---- t = 1..11 ----
#pragma unroll 1
        for (int t = 1; t < TT; t++) {
            asm volatile("bar.sync %0, %1;" :: "r"(bid), "n"(256) : "memory");

            const uint32_t rbase = (t & 1) ? ag1 : ag0;
            char* wbase = smem + (((t & 1) ? ag0 : ag1) - base);

            uint32_t a[2][8][4];
#pragma unroll
            for (int mt = 0; mt < 2; mt++)
#pragma unroll
                for (int kb = 0; kb < 8; kb++)
                    LDSM4(a[mt][kb][0], a[mt][kb][1], a[mt][kb][2], a[mt][kb][3],
                          rbase + a_rel + (uint32_t)mt * 16u * ROWB + (uint32_t)kb * 32u);

#pragma unroll
            for (int rr = 0; rr < 4; rr++) xr[rr] = xsg[(r0 + 8 * rr) * TT + t];

            uint32_t hw[4][2];

#pragma unroll 2
            for (int pp = 0; pp < 4; pp++) {
                const int u = 16 * Q + 4 * pp + j;
                const float4 kv = kp4[u];
                const float4 bv = bp4[u];

                // seed accumulators with x*k + bias (z complete after MMA chain)
                float d[16];
#pragma unroll
                for (int rr = 0; rr < 4; rr++) {
                    const int o = (rr >> 1) * 8 + (rr & 1) * 2;
                    d[o]     = fmaf(xr[rr], kv.x, bv.x);
                    d[o + 1] = fmaf(xr[rr], kv.y, bv.y);
                    d[o + 4] = fmaf(xr[rr], kv.z, bv.z);
                    d[o + 5] = fmaf(xr[rr], kv.w, bv.w);
                }

                const uint32_t bta = bt_base + (uint32_t)pp * (16u * ROWB);
#pragma unroll
                for (int kb = 0; kb < 8; kb++) {
                    uint32_t bq0, bq1, bq2, bq3;
                    LDSM4(bq0, bq1, bq2, bq3, bta + (uint32_t)kb * 32u);
                    MMA16816(d[0],  d[1],  d[2],  d[3],
                             a[0][kb][0], a[0][kb][1], a[0][kb][2], a[0][kb][3], bq0, bq2);
                    MMA16816(d[4],  d[5],  d[6],  d[7],
                             a[0][kb][0], a[0][kb][1], a[0][kb][2], a[0][kb][3], bq1, bq3);
                    MMA16816(d[8],  d[9],  d[10], d[11],
                             a[1][kb][0], a[1][kb][1], a[1][kb][2], a[1][kb][3], bq0, bq2);
                    MMA16816(d[12], d[13], d[14], d[15],
                             a[1][kb][0], a[1][kb][1], a[1][kb][2], a[1][kb][3], bq1, bq3);
                }

                // epilogue: d IS the pre-activation (i/f/o pre-halved)
#pragma unroll
                for (int rr = 0; rr < 4; rr++) {
                    const int o = (rr >> 1) * 8 + (rr & 1) * 2;
                    float ig = sigmoid_pre(d[o]);
                    float fg = sigmoid_pre(d[o + 1]);
                    float og = sigmoid_pre(d[o + 5]);
                    float cn = fmaf(fg, c[4 * pp + rr], ig * fmaxf(d[o + 4], 0.0f));
                    c[4 * pp + rr] = cn;
                    float hv = og * fmaxf(cn, 0.0f);
                    if ((pp & 1) == 0) {
                        __half2 h2 = __floats2half2_rn(hv, 0.0f);
                        hw[rr][pp >> 1] = *(uint32_t*)&h2;
                    } else {
                        __half2 h2; *(uint32_t*)&h2 = hw[rr][pp >> 1];
                        h2.y = __float2half(hv);
                        hw[rr][pp >> 1] = *(uint32_t*)&h2;
                    }
                }
            }

#pragma unroll
            for (int rr = 0; rr < 4; rr++)
                *(uint2*)(wbase + st_rel[rr]) = make_uint2(hw[rr][0], hw[rr][1]);
        }

        // ---- head: final h in buf0 (t=11 writes buf0).  y = h.Wd + bd ----
        asm volatile("bar.sync %0, %1;" :: "r"(bid), "n"(256) : "memory");
        {
            const int row = wtid >> 3, q = wtid & 7;    // 8 threads per row
            const __half* hrow = (const __half*)(smem + (ag0 - base)) + row * PADK + 16 * q;
            const float*  wq   = wdp + 16 * q;
            float s = 0.0f;
#pragma unroll
            for (int i = 0; i < 16; i += 2) {
                float2 hv = __half22float2(*(const __half2*)(hrow + i));
                s = fmaf(hv.x, wq[i], s);
                s = fmaf(hv.y, wq[i + 1], s);
            }
            redg[row * 8 + q] = s;
        }
        asm volatile("bar.sync %0, %1;" :: "r"(bid), "n"(256) : "memory");
        if (wtid < GTILE) {
            const float* p = redg + wtid * 8;
            float s = ((p[0] + p[1]) + (p[2] + p[3])) + ((p[4] + p[5]) + (p[6] + p[7]));
            out[b0 + wtid] = s + bd[0];
        }
        asm volatile("bar.sync %0, %1;" :: "r"(bid), "n"(256) : "memory");  // red reuse fence
    }
}

extern "C" void kernel_launch(void* const* d_in, const int* in_sizes, int n_in,
                              void* d_out, int out_size) {
    const float* x    = (const float*)d_in[0];
    const float* kern = (const float*)d_in[1];
    const float* rk   = (const float*)d_in[2];
    const float* bias = (const float*)d_in[3];
    const float* Wd   = (const float*)d_in[4];
    const float* bd   = (const float*)d_in[5];
    float* out = (float*)d_out;

    cudaFuncSetAttribute(lstm_kernel, cudaFuncAttributeMaxDynamicSharedMemorySize, SMEM_TOTAL);
    lstm_kernel<<<GRID, NTHREADS, SMEM_TOTAL>>>(x, kern, rk, bias, Wd, bd, out);
}

// round 11
// speedup vs baseline: 1.5206x; 1.0320x over previous
#include <cuda_runtime.h>
#include <cuda_fp16.h>
#include <cstdint>

// ==========================================================================
// LSTM (relu candidate/output) + linear head via mma.sync m16n8k16 fp16
// B=65536, T=12, F=1, H=128.
// R11: R10 + group-1 phase stagger (persistent anti-phasing of the two
//      independent 256-thread pipelines), register-resident output head
//      (t=11 peeled: ps += h*Wd in regs, no h writeback, 2 fewer barriers),
//      xr hoisted, simplified h2 packing.
// ==========================================================================

#define TT       12
#define HH       128
#define GG       512
#define GTILE    32                      // rows per group tile
#define NTHREADS 512
#define NGT      2048                    // 65536 / 32
#define GRID     148
#define NGROUPS  (GRID * 2)              // 296
#define PADK     136                     // halfs per row (128 data + 8 pad)
#define ROWB     (PADK * 2)              // 272 bytes
#define REDP     36                      // red row pitch (floats), bank-spread

// ---- shared memory layout (bytes) ----
#define BT_OFF    0
#define BT_BYTES  (GG * ROWB)            // 139264 : R^T fp16, i/f/o rows x0.5
#define A_BASE    (BT_OFF + BT_BYTES)    // 4 h buffers: [g][buf] 32x272
#define AG_BYTES  (GTILE * ROWB)         // 8704
#define KP_OFF    (A_BASE + 4 * AG_BYTES)        // float4[128] kernel (i/f/o x0.5)
#define BP_OFF    (KP_OFF + 2048)                // float4[128] bias (i/f/o x0.5)
#define XS_BASE   (BP_OFF + 2048)                // float[2][32*12]
#define RED_BASE  (XS_BASE + 2 * GTILE * TT * 4) // float[2][32*REDP]
#define SMEM_TOTAL (RED_BASE + 2 * GTILE * REDP * 4)

__device__ __forceinline__ uint32_t s2u(const void* p) {
    uint32_t a;
    asm("{ .reg .u64 t; cvta.to.shared.u64 t, %1; cvt.u32.u64 %0, t; }" : "=r"(a) : "l"(p));
    return a;
}

#define LDSM4(r0, r1, r2, r3, addr) \
    asm volatile("ldmatrix.sync.aligned.m8n8.x4.shared.b16 {%0,%1,%2,%3}, [%4];" \
                 : "=r"(r0), "=r"(r1), "=r"(r2), "=r"(r3) : "r"(addr))

#define MMA16816(d0, d1, d2, d3, a0, a1, a2, a3, b0, b1) \
    asm volatile("mma.sync.aligned.m16n8k16.row.col.f32.f16.f16.f32 " \
                 "{%0,%1,%2,%3}, {%4,%5,%6,%7}, {%8,%9}, {%0,%1,%2,%3};" \
                 : "+f"(d0), "+f"(d1), "+f"(d2), "+f"(d3) \
                 : "r"(a0), "r"(a1), "r"(a2), "r"(a3), "r"(b0), "r"(b1))

// Input v is PRE-HALVED (i/f/o weights scaled 0.5): sigmoid = 0.5*tanh(v)+0.5
__device__ __forceinline__ float sigmoid_pre(float v) {
    float t;
    asm("tanh.approx.f32 %0, %1;" : "=f"(t) : "f"(v));
    return fmaf(0.5f, t, 0.5f);
}

__global__ __launch_bounds__(NTHREADS, 1)
void lstm_kernel(const float* __restrict__ x, const float* __restrict__ kern,
                 const float* __restrict__ rk, const float* __restrict__ bias,
                 const float* __restrict__ Wd, const float* __restrict__ bd,
                 float* __restrict__ out) {
    extern __shared__ char smem[];
    const uint32_t base = s2u(smem);
    const int tid  = threadIdx.x;
    const int lane = tid & 31;
    const int wid  = tid >> 5;
    const int g    = wid >> 3;       // pipeline group 0/1 (8 warps each)
    const int Q    = wid & 7;        // N-eighth: 64 perm cols = 16 units
    const int wtid = tid & 255;      // thread id within group
    const int t4   = lane >> 2;
    const int j    = lane & 3;

    __half* bt  = (__half*)(smem + BT_OFF);
    float*  kp  = (float*)(smem + KP_OFF);
    float*  bp  = (float*)(smem + BP_OFF);
    float*  xsg = (float*)(smem + XS_BASE + g * (GTILE * TT * 4));
    float*  redg = (float*)(smem + RED_BASE + g * (GTILE * REDP * 4));

    // ---- one-time init (verified permutations + exact 0.5 prescale) ----
    for (int i = tid; i < HH * GG; i += NTHREADS) {
        int ks = i >> 9, col = i & 511;
        int u = col & 127, gt = col >> 7;
        int n = 16 * (u >> 2) + 8 * (gt >> 1) + 2 * (u & 3) + (gt & 1);
        int kk = (ks & 3) * 32 + (ks >> 2);
        float sc = (gt == 2) ? 1.0f : 0.5f;
        bt[n * PADK + kk] = __float2half(rk[i] * sc);
    }
    for (int col = tid; col < GG; col += NTHREADS) {
        int u = col & 127, gt = col >> 7;
        float sc = (gt == 2) ? 1.0f : 0.5f;
        kp[u * 4 + gt] = kern[col] * sc;
        bp[u * 4 + gt] = bias[col] * sc;
    }
    // head weights for this thread's 4 units (register-resident)
    float wdv[4];
#pragma unroll
    for (int pp = 0; pp < 4; pp++) wdv[pp] = Wd[16 * Q + 4 * pp + j];

    __syncthreads();   // ONLY CTA-wide sync; groups free-run afterwards

    // one-time phase stagger for group 1 -> persistent anti-phasing
    if (g == 1) {
#pragma unroll 1
        for (int i = 0; i < 160; i++) asm volatile("" ::: "memory");
    }

    const uint32_t ag0 = base + A_BASE + (uint32_t)g * 2u * AG_BYTES;
    const uint32_t ag1 = ag0 + AG_BYTES;

    const uint32_t lrow = (uint32_t)((lane & 7) + (lane & 8));
    const uint32_t lcol = (uint32_t)((lane >> 4) << 4);
    const uint32_t a_rel   = lrow * ROWB + lcol;
    const uint32_t bt_base = base + BT_OFF + ((uint32_t)Q * 64u + lrow) * ROWB + lcol;

    const int r0 = t4;
    uint32_t st_rel[4];
#pragma unroll
    for (int rr = 0; rr < 4; rr++)
        st_rel[rr] = (uint32_t)((r0 + 8 * rr) * ROWB + 64 * j + 8 * Q);

    const float4* kp4 = (const float4*)kp;
    const float4* bp4 = (const float4*)bp;
    const int bid = g + 1;

    // ---- persistent per-group tile loop ----
    for (int tile = blockIdx.x * 2 + g; tile < NGT; tile += NGROUPS) {
        const int b0 = tile * GTILE;

        for (int i = wtid; i < GTILE * TT; i += 256) xsg[i] = x[(size_t)b0 * TT + i];
        asm volatile("bar.sync %0, %1;" :: "r"(bid), "n"(256) : "memory");  // xs ready

        float c[16];
        float xr[4];
#pragma unroll
        for (int rr = 0; rr < 4; rr++) xr[rr] = xsg[(r0 + 8 * rr) * TT + 0];

        // ---- t = 0 peeled (h0=0): z = x*k + b ; writes buf1 ----
        {
            uint32_t hw[4][2];
            float hprev[4];
#pragma unroll
            for (int pp = 0; pp < 4; pp++) {
                const int u = 16 * Q + 4 * pp + j;
                const float4 kv = kp4[u];
                const float4 bv = bp4[u];
#pragma unroll
                for (int rr = 0; rr < 4; rr++) {
                    float zi = fmaf(xr[rr], kv.x, bv.x);
                    float zg = fmaf(xr[rr], kv.z, bv.z);
                    float zo = fmaf(xr[rr], kv.w, bv.w);
                    float ig = sigmoid_pre(zi), og = sigmoid_pre(zo);
                    float cn = ig * fmaxf(zg, 0.0f);
                    c[4 * pp + rr] = cn;
                    float hv = og * fmaxf(cn, 0.0f);
                    if ((pp & 1) == 0) hprev[rr] = hv;
                    else {
                        __half2 h2 = __floats2half2_rn(hprev[rr], hv);
                        hw[rr][pp >> 1] = *(uint32_t*)&h2;
                    }
                }
            }
#pragma unroll
            for (int rr = 0; rr < 4; rr++)
                *(uint2*)(smem + (ag1 - base) + st_rel[rr]) = make_uint2(hw[rr][0], hw[rr][1]);
        }

        // ---- t = 1..10 ----
#pragma unroll 1
        for (int t = 1; t < TT - 1; t++) {
            asm volatile("bar.sync %0, %1;" :: "r"(bid), "n"(256) : "memory");

            const uint32_t rbase = (t & 1) ? ag1 : ag0;
            char* wbase = smem + (((t & 1) ? ag0 : ag1) - base);

#pragma unroll
            for (int rr = 0; rr < 4; rr++) xr[rr] = xsg[(r0 + 8 * rr) * TT + t];

            uint32_t a[2][8][4];
#pragma unroll
            for (int mt = 0; mt < 2; mt++)
#pragma unroll
                for (int kb = 0; kb < 8; kb++)
                    LDSM4(a[mt][kb][0], a[mt][kb][1], a[mt][kb][2], a[mt][kb][3],
                          rbase + a_rel + (uint32_t)mt * 16u * ROWB + (uint32_t)kb * 32u);

            uint32_t hw[4][2];
            float hprev[4];

#pragma unroll 2
            for (int pp = 0; pp < 4; pp++) {
                const int u = 16 * Q + 4 * pp + j;
                const float4 kv = kp4[u];
                const float4 bv = bp4[u];

                float d[16];
#pragma unroll
                for (int rr = 0; rr < 4; rr++) {
                    const int o = (rr >> 1) * 8 + (rr & 1) * 2;
                    d[o]     = fmaf(xr[rr], kv.x, bv.x);
                    d[o + 1] = fmaf(xr[rr], kv.y, bv.y);
                    d[o + 4] = fmaf(xr[rr], kv.z, bv.z);
                    d[o + 5] = fmaf(xr[rr], kv.w, bv.w);
                }

                const uint32_t bta = bt_base + (uint32_t)pp * (16u * ROWB);
#pragma unroll
                for (int kb = 0; kb < 8; kb++) {
                    uint32_t bq0, bq1, bq2, bq3;
                    LDSM4(bq0, bq1, bq2, bq3, bta + (uint32_t)kb * 32u);
                    MMA16816(d[0],  d[1],  d[2],  d[3],
                             a[0][kb][0], a[0][kb][1], a[0][kb][2], a[0][kb][3], bq0, bq2);
                    MMA16816(d[4],  d[5],  d[6],  d[7],
                             a[0][kb][0], a[0][kb][1], a[0][kb][2], a[0][kb][3], bq1, bq3);
                    MMA16816(d[8],  d[9],  d[10], d[11],
                             a[1][kb][0], a[1][kb][1], a[1][kb][2], a[1][kb][3], bq0, bq2);
                    MMA16816(d[12], d[13], d[14], d[15],
                             a[1][kb][0], a[1][kb][1], a[1][kb][2], a[1][kb][3], bq1, bq3);
                }

#pragma unroll
                for (int rr = 0; rr < 4; rr++) {
                    const int o = (rr >> 1) * 8 + (rr & 1) * 2;
                    float ig = sigmoid_pre(d[o]);
                    float fg = sigmoid_pre(d[o + 1]);
                    float og = sigmoid_pre(d[o + 5]);
                    float cn = fmaf(fg, c[4 * pp + rr], ig * fmaxf(d[o + 4], 0.0f));
                    c[4 * pp + rr] = cn;
                    float hv = og * fmaxf(cn, 0.0f);
                    if ((pp & 1) == 0) hprev[rr] = hv;
                    else {
                        __half2 h2 = __floats2half2_rn(hprev[rr], hv);
                        hw[rr][pp >> 1] = *(uint32_t*)&h2;
                    }
                }
            }

#pragma unroll
            for (int rr = 0; rr < 4; rr++)
                *(uint2*)(wbase + st_rel[rr]) = make_uint2(hw[rr][0], hw[rr][1]);
        }

        // ---- t = 11 peeled: no h writeback; ps = sum h*Wd in regs ----
        {
            asm volatile("bar.sync %0, %1;" :: "r"(bid), "n"(256) : "memory");
            const uint32_t rbase = ag1;   // t=11 odd -> reads buf1

#pragma unroll
            for (int rr = 0; rr < 4; rr++) xr[rr] = xsg[(r0 + 8 * rr) * TT + 11];

            uint32_t a[2][8][4];
#pragma unroll
            for (int mt = 0; mt < 2; mt++)
#pragma unroll
                for (int kb = 0; kb < 8; kb++)
                    LDSM4(a[mt][kb][0], a[mt][kb][1], a[mt][kb][2], a[mt][kb][3],
                          rbase + a_rel + (uint32_t)mt * 16u * ROWB + (uint32_t)kb * 32u);

            float ps[4] = {0.f, 0.f, 0.f, 0.f};

#pragma unroll 2
            for (int pp = 0; pp < 4; pp++) {
                const int u = 16 * Q + 4 * pp + j;
                const float4 kv = kp4[u];
                const float4 bv = bp4[u];

                float d[16];
#pragma unroll
                for (int rr = 0; rr < 4; rr++) {
                    const int o = (rr >> 1) * 8 + (rr & 1) * 2;
                    d[o]     = fmaf(xr[rr], kv.x, bv.x);
                    d[o + 1] = fmaf(xr[rr], kv.y, bv.y);
                    d[o + 4] = fmaf(xr[rr], kv.z, bv.z);
                    d[o + 5] = fmaf(xr[rr], kv.w, bv.w);
                }

                const uint32_t bta = bt_base + (uint32_t)pp * (16u * ROWB);
#pragma unroll
                for (int kb = 0; kb < 8; kb++) {
                    uint32_t bq0, bq1, bq2, bq3;
                    LDSM4(bq0, bq1, bq2, bq3, bta + (uint32_t)kb * 32u);
                    MMA16816(d[0],  d[1],  d[2],  d[3],
                             a[0][kb][0], a[0][kb][1], a[0][kb][2], a[0][kb][3], bq0, bq2);
                    MMA16816(d[4],  d[5],  d[6],  d[7],
                             a[0][kb][0], a[0][kb][1], a[0][kb][2], a[0][kb][3], bq1, bq3);
                    MMA16816(d[8],  d[9],  d[10], d[11],
                             a[1][kb][0], a[1][kb][1], a[1][kb][2], a[1][kb][3], bq0, bq2);
                    MMA16816(d[12], d[13], d[14], d[15],
                             a[1][kb][0], a[1][kb][1], a[1][kb][2], a[1][kb][3], bq1, bq3);
                }

#pragma unroll
                for (int rr = 0; rr < 4; rr++) {
                    const int o = (rr >> 1) * 8 + (rr & 1) * 2;
                    float ig = sigmoid_pre(d[o]);
                    float fg = sigmoid_pre(d[o + 1]);
                    float og = sigmoid_pre(d[o + 5]);
                    float cn = fmaf(fg, c[4 * pp + rr], ig * fmaxf(d[o + 4], 0.0f));
                    float hv = og * fmaxf(cn, 0.0f);
                    ps[rr] = fmaf(hv, wdv[pp], ps[rr]);
                }
            }

            // red[row][Q*4+j], pitch REDP floats (bank-spread)
#pragma unroll
            for (int rr = 0; rr < 4; rr++)
                redg[(r0 + 8 * rr) * REDP + Q * 4 + j] = ps[rr];
        }

        asm volatile("bar.sync %0, %1;" :: "r"(bid), "n"(256) : "memory");
        if (wtid < GTILE) {
            const float4* p = (const float4*)(redg + wtid * REDP);
            float4 s0 = p[0], s1 = p[1], s2 = p[2], s3 = p[3];
            float4 s4 = p[4], s5 = p[5], s6 = p[6], s7 = p[7];
            float s = (((s0.x + s0.y) + (s0.z + s0.w)) + ((s1.x + s1.y) + (s1.z + s1.w)))
                    + (((s2.x + s2.y) + (s2.z + s2.w)) + ((s3.x + s3.y) + (s3.z + s3.w)))
                    + (((s4.x + s4.y) + (s4.z + s4.w)) + ((s5.x + s5.y) + (s5.z + s5.w)))
                    + (((s6.x + s6.y) + (s6.z + s6.w)) + ((s7.x + s7.y) + (s7.z + s7.w)));
            out[b0 + wtid] = s + bd[0];
        }
        // next-tile xs/red writes are ordered by the xs-ready barrier above
    }
}

extern "C" void kernel_launch(void* const* d_in, const int* in_sizes, int n_in,
                              void* d_out, int out_size) {
    const float* x    = (const float*)d_in[0];
    const float* kern = (const float*)d_in[1];
    const float* rk   = (const float*)d_in[2];
    const float* bias = (const float*)d_in[3];
    const float* Wd   = (const float*)d_in[4];
    const float* bd   = (const float*)d_in[5];
    float* out = (float*)d_out;

    cudaFuncSetAttribute(lstm_kernel, cudaFuncAttributeMaxDynamicSharedMemorySize, SMEM_TOTAL);
    lstm_kernel<<<GRID, NTHREADS, SMEM_TOTAL>>>(x, kern, rk, bias, Wd, bd, out);
}